// round 3
// baseline (speedup 1.0000x reference)
#include <cuda_runtime.h>
#include <stdint.h>

// Problem constants (fixed: N=8192, E=262144, C=256, H=256, MC=256)
#define NN 8192
#define EE 262144
#define CC 256

// Algebraic collapse (validated in round 2, rel_err 5e-7):
//   S = softmax(assign) is the uniform 1/256 matrix, so
//   x_pooled[j,c]   = (1/256) * sum_n x[n,c]        (all 256 rows identical)
//   adj_pooled[i,j] = nnz_unique(row,col) / 65536   (scalar; adj .set() dedupes)

// Scratch (__device__ globals; no allocations allowed).
__device__ unsigned int g_bitmap[(NN * (long long)NN) / 32];  // 8 MB uniqueness bitmap
__device__ float g_partial[128 * CC];                         // per-block column partials
__device__ int   g_count;                                     // unique edge count
__device__ int   g_arrive;                                    // last-block ticket

// ---------------------------------------------------------------------------
// Kernel 1: zero bitmap + scalars (every launch, for graph replay idempotence).
// 524,288 uint4 = grid 2048 x 256.
__global__ void __launch_bounds__(256) k_zero_bitmap() {
    uint4* p = reinterpret_cast<uint4*>(g_bitmap);
    int i = blockIdx.x * blockDim.x + threadIdx.x;
    p[i] = make_uint4(0u, 0u, 0u, 0u);
    if (i == 0) { g_count = 0; g_arrive = 0; }
}

// ---------------------------------------------------------------------------
// Kernel 2: mark edges, count newly-set bits. Grid 1024 x 256 (1 thread/edge).
// edge_index is int32 on device (JAX default config downcasts jnp.int64).
__global__ void __launch_bounds__(256) k_edges(const int* __restrict__ ei) {
    int e = blockIdx.x * blockDim.x + threadIdx.x;
    int r = ei[e];        // edge_index[0, e]
    int c = ei[EE + e];   // edge_index[1, e]
    unsigned idx = (unsigned)r * (unsigned)NN + (unsigned)c;   // < 2^26
    unsigned m = 1u << (idx & 31u);
    unsigned old = atomicOr(&g_bitmap[idx >> 5], m);
    int nb = (old & m) ? 0 : 1;

    unsigned ball = __ballot_sync(0xffffffffu, nb);
    __shared__ int s[8];
    int lane = threadIdx.x & 31;
    int w = threadIdx.x >> 5;
    if (lane == 0) s[w] = __popc(ball);
    __syncthreads();
    if (threadIdx.x == 0) {
        int t = 0;
#pragma unroll
        for (int i = 0; i < 8; i++) t += s[i];
        atomicAdd(&g_count, t);   // 1024 single-address REDs total: cheap, deterministic
    }
}

// ---------------------------------------------------------------------------
// Kernel 3: column sums of x + last-block final reduce + full output write.
// Grid 128 x 1024. Block b covers rows [b*64, b*64+64); thread (c = t&255,
// q = t>>8) sums 16 rows. Fixed-order float trees -> deterministic.
__global__ void __launch_bounds__(1024) k_colsum_final(const float* __restrict__ x,
                                                       float* __restrict__ out) {
    __shared__ float sm[1024];
    int t = threadIdx.x;
    int c = t & 255;
    int q = t >> 8;          // 0..3
    int b = blockIdx.x;      // 0..127

    // Stage 1: per-thread partial over 16 rows (coalesced: lane = column).
    int r0 = b * 64 + q * 16;
    float s = 0.0f;
#pragma unroll
    for (int i = 0; i < 16; i++) s += x[(size_t)(r0 + i) * CC + c];
    sm[t] = s;
    __syncthreads();
    if (q == 0)
        g_partial[b * CC + c] = sm[c] + sm[256 + c] + sm[512 + c] + sm[768 + c];

    // Last-block election.
    __threadfence();
    __shared__ int ticket;
    if (t == 0) ticket = atomicAdd(&g_arrive, 1);
    __syncthreads();
    if (ticket != 127) return;

    // Stage 2 (one block, 4-way parallel over the partial axis): 32 iters/thread.
    float acc = 0.0f;
#pragma unroll 8
    for (int bb = q * 32; bb < q * 32 + 32; bb++) acc += g_partial[bb * CC + c];
    __syncthreads();
    sm[t] = acc;
    __syncthreads();

    __shared__ float cs[256];     // colsum / 256 (= x_pooled row value)
    if (q == 0)
        cs[c] = (sm[c] + sm[256 + c] + sm[512 + c] + sm[768 + c]) * (1.0f / 256.0f);
    __syncthreads();

    // Output write. Layout: [x_pooled (256x256) | adj_pooled (256x256)].
    // g_count is visible: k_edges completed earlier in stream order.
    float4* out4 = reinterpret_cast<float4*>(out);
    float av = (float)g_count * (1.0f / 65536.0f);
    float4 a4 = make_float4(av, av, av, av);
#pragma unroll
    for (int j = t; j < 16384; j += 1024) {
        int cb = 4 * (j & 63);                        // (4j) & 255
        out4[j] = make_float4(cs[cb], cs[cb + 1], cs[cb + 2], cs[cb + 3]);
        out4[16384 + j] = a4;
    }
}

// ---------------------------------------------------------------------------
extern "C" void kernel_launch(void* const* d_in, const int* in_sizes, int n_in,
                              void* d_out, int out_size) {
    const float* x  = (const float*)d_in[0];   // (N, C) f32
    const int*   ei = (const int*)d_in[1];     // (2, E) i32
    float* out = (float*)d_out;

    k_zero_bitmap<<<2048, 256>>>();
    k_edges<<<1024, 256>>>(ei);
    k_colsum_final<<<128, 1024>>>(x, out);
}

// round 4
// speedup vs baseline: 1.5529x; 1.5529x over previous
#include <cuda_runtime.h>
#include <stdint.h>

// Problem constants (fixed: N=8192, E=262144, C=256, H=256, MC=256)
#define NN 8192
#define EE 262144
#define CC 256
#define NBLK 128          // all co-resident on 148 SMs -> grid barrier is safe
#define NTHR 1024

// Algebraic collapse (validated: rel_err ~4e-7):
//   S = softmax(assign) is the uniform 1/256 matrix, so
//   x_pooled[j,c]   = (1/256) * sum_n x[n,c]        (all 256 rows identical)
//   adj_pooled[i,j] = nnz_unique(row,col) / 65536   (scalar; adj .set() dedupes)

// Scratch (__device__ globals, zero-initialized at module load; the kernel
// restores all of it to zero before exiting, so graph replays are idempotent
// and NO memset kernel is needed).
__device__ unsigned int g_bitmap[(NN * (long long)NN) / 32];  // 8 MB, L2-resident
__device__ float g_partial[NBLK * CC];
__device__ int   g_count;   // unique edge count
__device__ int   g_bar;     // grid barrier arrivals
__device__ int   g_done;    // finish tickets

__global__ void __launch_bounds__(NTHR) k_fused(const float* __restrict__ x,
                                                const int* __restrict__ ei,
                                                float* __restrict__ out) {
    __shared__ float sm[NTHR];
    __shared__ int   swc[32];
    __shared__ float cs[CC];

    const int t = threadIdx.x;
    const int b = blockIdx.x;
    const int c = t & 255;
    const int q = t >> 8;                  // 0..3
    const int lane = t & 31, w = t >> 5;

    // ---------------- Phase A: edges (mark + count) --------------------------
    // 131072 threads x 2 edges each = 262144. edge_index is int32 on device
    // (JAX default config downcasts jnp.int64).
    const int e0 = (b * NTHR + t) * 2;
    const int r0e = ei[e0],     c0e = ei[EE + e0];
    const int r1e = ei[e0 + 1], c1e = ei[EE + e0 + 1];
    const unsigned idx0 = (unsigned)r0e * NN + (unsigned)c0e;   // < 2^26
    const unsigned idx1 = (unsigned)r1e * NN + (unsigned)c1e;

    unsigned m0 = 1u << (idx0 & 31u);
    unsigned m1 = 1u << (idx1 & 31u);
    unsigned o0 = atomicOr(&g_bitmap[idx0 >> 5], m0);
    unsigned o1 = atomicOr(&g_bitmap[idx1 >> 5], m1);
    int nb = ((o0 & m0) ? 0 : 1) + ((o1 & m1) ? 0 : 1);

    // Deterministic integer block reduce -> one atomicAdd per block.
#pragma unroll
    for (int o = 16; o > 0; o >>= 1) nb += __shfl_down_sync(0xffffffffu, nb, o);
    if (lane == 0) swc[w] = nb;

    // ---------------- Phase A: column partial sums of x ----------------------
    // Block b covers rows [b*64, b*64+64); thread (c, q) sums 16 rows.
    {
        int r0 = b * 64 + q * 16;
        float s = 0.0f;
#pragma unroll
        for (int i = 0; i < 16; i++) s += x[(size_t)(r0 + i) * CC + c];
        sm[t] = s;
    }
    __syncthreads();
    if (t == 0) {
        int tc = 0;
#pragma unroll
        for (int i = 0; i < 32; i++) tc += swc[i];
        atomicAdd(&g_count, tc);
    }
    if (q == 0)
        g_partial[b * CC + c] = sm[c] + sm[256 + c] + sm[512 + c] + sm[768 + c];

    // ---------------- Grid barrier ------------------------------------------
    __threadfence();
    __syncthreads();
    if (t == 0) {
        atomicAdd(&g_bar, 1);
        while (*(volatile int*)&g_bar < NBLK) { __nanosleep(64); }
    }
    __syncthreads();

    // ---------------- Phase B: restore bitmap invariant ----------------------
    // Clear exactly the words we marked (scattered 4B stores, L2-resident).
    g_bitmap[idx0 >> 5] = 0u;
    g_bitmap[idx1 >> 5] = 0u;

    // ---------------- Phase B: final colsum (every block, independently) -----
    float acc = 0.0f;
#pragma unroll 8
    for (int bb = q * 32; bb < q * 32 + 32; bb++) acc += g_partial[bb * CC + c];
    sm[t] = acc;
    __syncthreads();
    if (q == 0)
        cs[c] = (sm[c] + sm[256 + c] + sm[512 + c] + sm[768 + c]) * (1.0f / 256.0f);
    __syncthreads();

    // ---------------- Phase B: output slice ----------------------------------
    // Layout: [x_pooled (256x256) | adj_pooled (256x256)]. Block b writes rows
    // {2b, 2b+1} of each half: 256 float4s, threads 0..255.
    if (t < 256) {
        float4* out4 = reinterpret_cast<float4*>(out);
        if (t < 128) {
            int j = 2 * b + (t >> 6);
            int cb = (t & 63) * 4;
            out4[j * 64 + (t & 63)] =
                make_float4(cs[cb], cs[cb + 1], cs[cb + 2], cs[cb + 3]);
        } else {
            int tt = t - 128;
            int j = 2 * b + (tt >> 6);
            float av = (float)g_count * (1.0f / 65536.0f);
            out4[16384 + j * 64 + (tt & 63)] = make_float4(av, av, av, av);
        }
    }
    __syncthreads();

    // ---------------- Reset scalars for the next replay ----------------------
    if (t == 0) {
        int d = atomicAdd(&g_done, 1);
        if (d == NBLK - 1) { g_bar = 0; g_done = 0; g_count = 0; }
    }
}

extern "C" void kernel_launch(void* const* d_in, const int* in_sizes, int n_in,
                              void* d_out, int out_size) {
    const float* x  = (const float*)d_in[0];   // (N, C) f32
    const int*   ei = (const int*)d_in[1];     // (2, E) i32
    float* out = (float*)d_out;
    k_fused<<<NBLK, NTHR>>>(x, ei, out);
}

// round 5
// speedup vs baseline: 1.8020x; 1.1604x over previous
#include <cuda_runtime.h>
#include <stdint.h>

// Problem constants (fixed: N=8192, E=262144, C=256, H=256, MC=256)
#define NN 8192
#define EE 262144
#define CC 256
#define NBLK 128          // all co-resident on 148 SMs -> grid barrier is safe
#define NTHR 1024

// Algebraic collapse (validated: rel_err ~4e-7):
//   S = softmax(assign) is the uniform 1/256 matrix, so
//   x_pooled[j,c]   = (1/256) * sum_n x[n,c]        (all 256 rows identical)
//   adj_pooled[i,j] = nnz_unique(row,col) / 65536   (scalar; adj .set() dedupes)

// Scratch (__device__ globals, zero at module load; kernel restores all state
// to zero before exit -> graph replays are idempotent, no memset kernel).
__device__ unsigned int g_bitmap[(NN * (long long)NN) / 32];  // 8 MB, L2-resident
__device__ float g_partial[NBLK * CC];   // [block][column] colsum partials
__device__ int   g_count;                // unique edge count
__device__ int   g_bar;                  // grid barrier arrivals
__device__ int   g_done;                 // finish tickets

__global__ void __launch_bounds__(NTHR) k_fused(const float* __restrict__ x,
                                                const int* __restrict__ ei,
                                                float* __restrict__ out) {
    __shared__ float4 sm4[NTHR];         // 16 KB
    __shared__ int    swc[32];
    __shared__ float  smr[256];

    const int t = threadIdx.x;
    const int b = blockIdx.x;
    const int lane = t & 31, w = t >> 5;

    // ---------------- Phase A: edges (mark + count) --------------------------
    // 131072 threads x 2 edges. edge_index is int32 (JAX downcasts jnp.int64);
    // the two edges per thread are adjacent -> int2 loads.
    const int2* ei2 = reinterpret_cast<const int2*>(ei);
    const int ep = b * NTHR + t;                 // pair index
    const int2 rp = ei2[ep];
    const int2 cp = ei2[EE / 2 + ep];
    const unsigned idx0 = (unsigned)rp.x * NN + (unsigned)cp.x;   // < 2^26
    const unsigned idx1 = (unsigned)rp.y * NN + (unsigned)cp.y;

    unsigned m0 = 1u << (idx0 & 31u);
    unsigned m1 = 1u << (idx1 & 31u);
    unsigned o0 = atomicOr(&g_bitmap[idx0 >> 5], m0);
    unsigned o1 = atomicOr(&g_bitmap[idx1 >> 5], m1);
    int nb = ((o0 & m0) ? 0 : 1) + ((o1 & m1) ? 0 : 1);

#pragma unroll
    for (int o = 16; o > 0; o >>= 1) nb += __shfl_down_sync(0xffffffffu, nb, o);
    if (lane == 0) swc[w] = nb;

    // ---------------- Phase A: column partial sums of x (float4) -------------
    // Block b covers rows [b*64, b*64+64). g = float4 column group (0..63),
    // q = row sub-group (0..15), 4 rows per thread. Coalesced 16B loads.
    {
        const float4* x4 = reinterpret_cast<const float4*>(x);
        int g = t & 63, q = t >> 6;
        int r0 = b * 64 + q * 4;
        float4 a = x4[(size_t)r0 * 64 + g];
        float4 v1 = x4[(size_t)(r0 + 1) * 64 + g];
        float4 v2 = x4[(size_t)(r0 + 2) * 64 + g];
        float4 v3 = x4[(size_t)(r0 + 3) * 64 + g];
        a.x += v1.x; a.y += v1.y; a.z += v1.z; a.w += v1.w;
        a.x += v2.x; a.y += v2.y; a.z += v2.z; a.w += v2.w;
        a.x += v3.x; a.y += v3.y; a.z += v3.z; a.w += v3.w;
        sm4[t] = a;
    }
    __syncthreads();
    if (t == 0) {
        int tc = 0;
#pragma unroll
        for (int i = 0; i < 32; i++) tc += swc[i];
        atomicAdd(&g_count, tc);
    }
    if (t < 64) {
        // Fixed-order sum over the 16 q-groups -> deterministic.
        float4 s = sm4[t];
#pragma unroll
        for (int k = 1; k < 16; k++) {
            float4 v = sm4[k * 64 + t];
            s.x += v.x; s.y += v.y; s.z += v.z; s.w += v.w;
        }
        reinterpret_cast<float4*>(g_partial)[b * 64 + t] = s;
    }

    // ---------------- Grid barrier ------------------------------------------
    __threadfence();
    __syncthreads();
    if (t == 0) {
        atomicAdd(&g_bar, 1);
        while (*(volatile int*)&g_bar < NBLK) { __nanosleep(64); }
    }
    __syncthreads();

    // ---------------- Phase B: restore bitmap invariant ----------------------
    g_bitmap[idx0 >> 5] = 0u;
    g_bitmap[idx1 >> 5] = 0u;

    // ---------------- Phase B: finalize columns {2b, 2b+1} only --------------
    // Thread i<256: bb = i>>1, col = 2b + (i&1). 1 KB of partial reads/block.
    if (t < 256) {
        int bb = t >> 1, h = t & 1;
        smr[h * 128 + bb] = g_partial[bb * CC + 2 * b + h];
    }
    __syncthreads();
    // Two parallel 128-way fixed trees (halves h=0,1).
    if (t < 256) {
        int h = t >> 7, j = t & 127;
#pragma unroll
        for (int o = 64; o > 0; o >>= 1) {
            if (j < o) smr[h * 128 + j] += smr[h * 128 + j + o];
            __syncwarp();                       // j<64 fits... need block sync
        }
    }
    __syncthreads();   // conservative re-sync (tree above uses full smem barrier below)

    // NOTE: the loop above relies on intra-warp sync only once o<32; redo the
    // wide steps safely: recompute with explicit block-wide barriers instead.
    // (Correctness-first: do the whole tree again with __syncthreads().)
    if (t < 256) {
        int bb = t >> 1, h = t & 1;
        smr[h * 128 + bb] = g_partial[bb * CC + 2 * b + h];
    }
    __syncthreads();
#pragma unroll
    for (int o = 64; o > 0; o >>= 1) {
        if (t < 256) {
            int h = t >> 7, j = t & 127;
            if (j < o) smr[h * 128 + j] += smr[h * 128 + j + o];
        }
        __syncthreads();
    }

    // ---------------- Phase B: write columns {2b, 2b+1} of both halves -------
    {
        float cs0 = smr[0]   * (1.0f / 256.0f);
        float cs1 = smr[128] * (1.0f / 256.0f);
        float av  = (float)g_count * (1.0f / 65536.0f);
        if (t < 256) {
            float2* o2 = reinterpret_cast<float2*>(out + (size_t)t * CC + 2 * b);
            *o2 = make_float2(cs0, cs1);
            float2* a2 = reinterpret_cast<float2*>(out + 65536 + (size_t)t * CC + 2 * b);
            *a2 = make_float2(av, av);
        }
    }
    __syncthreads();

    // ---------------- Reset scalars for next replay --------------------------
    if (t == 0) {
        int d = atomicAdd(&g_done, 1);
        if (d == NBLK - 1) { g_bar = 0; g_done = 0; g_count = 0; }
    }
}

extern "C" void kernel_launch(void* const* d_in, const int* in_sizes, int n_in,
                              void* d_out, int out_size) {
    const float* x  = (const float*)d_in[0];   // (N, C) f32
    const int*   ei = (const int*)d_in[1];     // (2, E) i32
    float* out = (float*)d_out;
    k_fused<<<NBLK, NTHR>>>(x, ei, out);
}